// round 2
// baseline (speedup 1.0000x reference)
#include <cuda_runtime.h>
#include <cstdint>

#define DEVINL __device__ __forceinline__

// ---------------- problem sizes ----------------
constexpr int Bb = 32, Ss = 2048, Hh = 1024;
constexpr int M_TOTAL = Bb * Ss;          // 65536
constexpr int BM = 128, BN = 256, BK = 32;
constexpr int NSTEPS = Hh / BK;           // 32
constexpr int NT = Hh / BN;               // 4 N-tiles
constexpr int LDA = 36;                   // padded smem row stride (floats)

// ---------------- scratch (no allocs allowed) ----------------
__device__ float g_ws[Bb * Hh];           // W_s @ dec
__device__ float g_wh_t[Hh * Hh];         // tf32-rounded W_h
__device__ float g_part[NT][M_TOTAL];     // partial scores per N-tile

struct SmemK1 {
    float A[2][BM][LDA];      // 36,864 B
    float B[2][BN][LDA];      // 73,728 B
    float ws[BN];
    float v[BN];
    float rowsum[BM];
};

// ---------------- helpers ----------------
DEVINL uint32_t smem_u32(const void* p) {
    uint32_t a;
    asm("{ .reg .u64 t; cvta.to.shared.u64 t, %1; cvt.u32.u64 %0, t; }" : "=r"(a) : "l"(p));
    return a;
}
DEVINL uint32_t cvt_rna_tf32(float x) {
    uint32_t r;
    asm("cvt.rna.tf32.f32 %0, %1;" : "=r"(r) : "f"(x));
    return r;
}
DEVINL float tanh_fast(float x) {
    float r;
    asm("tanh.approx.f32 %0, %1;" : "=f"(r) : "f"(x));
    return r;
}
DEVINL void cp_async16(uint32_t dst, const void* src) {
    asm volatile("cp.async.cg.shared.global [%0], [%1], 16;" :: "r"(dst), "l"(src));
}
DEVINL void cp_commit() { asm volatile("cp.async.commit_group;"); }
DEVINL void cp_wait0()  { asm volatile("cp.async.wait_group 0;"); }

DEVINL void mma_tf32(float c[4], const uint32_t a[4], const uint32_t b[2]) {
    asm volatile(
        "mma.sync.aligned.m16n8k8.row.col.f32.tf32.tf32.f32 "
        "{%0,%1,%2,%3}, {%4,%5,%6,%7}, {%8,%9}, {%0,%1,%2,%3};"
        : "+f"(c[0]), "+f"(c[1]), "+f"(c[2]), "+f"(c[3])
        : "r"(a[0]), "r"(a[1]), "r"(a[2]), "r"(a[3]), "r"(b[0]), "r"(b[1]));
}

// ================= K0a: round W_h to tf32 (rna) once =================
__global__ void round_wh_kernel(const float* __restrict__ Wh) {
    int i = (blockIdx.x * 256 + threadIdx.x) * 4;
    float4 v = *reinterpret_cast<const float4*>(Wh + i);
    uint4 u;
    u.x = cvt_rna_tf32(v.x); u.y = cvt_rna_tf32(v.y);
    u.z = cvt_rna_tf32(v.z); u.w = cvt_rna_tf32(v.w);
    *reinterpret_cast<uint4*>(g_wh_t + i) = u;
}

// ================= K0b: ws[b,o] = dec[b,:] . W_s[o,:] (fp32 exact) =================
__global__ void ws_kernel(const float* __restrict__ dec, const float* __restrict__ Wsm) {
    int idx = blockIdx.x * 8 + (threadIdx.x >> 5);   // 32768 outputs, 1 warp each
    int lid = threadIdx.x & 31;
    int b = idx >> 10, o = idx & 1023;
    const float* dr = dec + (size_t)b * Hh;
    const float* wr = Wsm + (size_t)o * Hh;
    float acc = 0.f;
#pragma unroll
    for (int i = 0; i < 8; i++) {
        int k = (i * 32 + lid) * 4;
        float4 d4 = *reinterpret_cast<const float4*>(dr + k);
        float4 w4 = *reinterpret_cast<const float4*>(wr + k);
        acc += d4.x * w4.x + d4.y * w4.y + d4.z * w4.z + d4.w * w4.w;
    }
#pragma unroll
    for (int off = 16; off; off >>= 1) acc += __shfl_xor_sync(0xffffffffu, acc, off);
    if (lid == 0) g_ws[idx] = acc;
}

// ================= K1: fused tf32 GEMM + tanh + v-dot -> partial scores =================
__global__ __launch_bounds__(256, 1) void attn_scores_kernel(
    const float* __restrict__ enc, const float* __restrict__ vvec) {
    extern __shared__ char smraw[];
    SmemK1& sm = *reinterpret_cast<SmemK1*>(smraw);

    int tid = threadIdx.x, wid = tid >> 5, lane = tid & 31;
    int g = lane >> 2, t = lane & 3;
    int wm = (wid >> 2) * 64, wn = (wid & 3) * 64;
    int m_base = blockIdx.y * BM;
    int n_base = blockIdx.x * BN;
    int b = m_base >> 11;          // 2048 rows per batch, 128 | 2048

    for (int i = tid; i < BN; i += 256) {
        sm.ws[i] = g_ws[b * Hh + n_base + i];
        sm.v[i]  = vvec[n_base + i];
    }
    if (tid < BM) sm.rowsum[tid] = 0.f;

    const float* encp = enc + (size_t)m_base * Hh;

    // staging: A 1024 chunks (4/thread), B 2048 chunks (8/thread)
    int arow[4], acol[4];
#pragma unroll
    for (int i = 0; i < 4; i++) { int cid = tid + i * 256; arow[i] = cid >> 3; acol[i] = cid & 7; }

    float4 ar[4];
    auto ldgA = [&](int k0) {
#pragma unroll
        for (int i = 0; i < 4; i++)
            ar[i] = *reinterpret_cast<const float4*>(encp + (size_t)arow[i] * Hh + k0 + acol[i] * 4);
    };
    auto stsA = [&](int p) {
#pragma unroll
        for (int i = 0; i < 4; i++) {
            uint4 u;
            u.x = cvt_rna_tf32(ar[i].x); u.y = cvt_rna_tf32(ar[i].y);
            u.z = cvt_rna_tf32(ar[i].z); u.w = cvt_rna_tf32(ar[i].w);
            *reinterpret_cast<uint4*>(&sm.A[p][arow[i]][acol[i] * 4]) = u;
        }
    };
    auto cpB = [&](int p, int k0) {
#pragma unroll
        for (int i = 0; i < 8; i++) {
            int cid = tid + i * 256; int r = cid >> 3, c = cid & 7;
            cp_async16(smem_u32(&sm.B[p][r][c * 4]),
                       g_wh_t + (size_t)(n_base + r) * Hh + k0 + c * 4);
        }
        cp_commit();
    };

    float acc[4][8][4];
#pragma unroll
    for (int ma = 0; ma < 4; ma++)
#pragma unroll
        for (int na = 0; na < 8; na++)
#pragma unroll
            for (int r = 0; r < 4; r++) acc[ma][na][r] = 0.f;

    // prologue
    ldgA(0); cpB(0, 0);
    stsA(0);
    cp_wait0();
    __syncthreads();

#pragma unroll 1
    for (int s = 0; s < NSTEPS; s++) {
        int p = s & 1;
        if (s + 1 < NSTEPS) { ldgA((s + 1) * BK); cpB(1 - p, (s + 1) * BK); }

#pragma unroll
        for (int ka = 0; ka < 4; ka++) {
            uint32_t af[4][4];
#pragma unroll
            for (int ma = 0; ma < 4; ma++) {
                const float* base = &sm.A[p][wm + ma * 16][0];
                af[ma][0] = __float_as_uint(base[(size_t)g * LDA + ka * 8 + t]);
                af[ma][1] = __float_as_uint(base[(size_t)(g + 8) * LDA + ka * 8 + t]);
                af[ma][2] = __float_as_uint(base[(size_t)g * LDA + ka * 8 + t + 4]);
                af[ma][3] = __float_as_uint(base[(size_t)(g + 8) * LDA + ka * 8 + t + 4]);
            }
            uint32_t bf[8][2];
#pragma unroll
            for (int na = 0; na < 8; na++) {
                const float* bb = &sm.B[p][wn + na * 8 + g][0];
                bf[na][0] = __float_as_uint(bb[ka * 8 + t]);
                bf[na][1] = __float_as_uint(bb[ka * 8 + t + 4]);
            }
#pragma unroll
            for (int ma = 0; ma < 4; ma++)
#pragma unroll
                for (int na = 0; na < 8; na++)
                    mma_tf32(acc[ma][na], af[ma], bf[na]);
        }

        if (s + 1 < NSTEPS) { stsA(1 - p); cp_wait0(); }
        __syncthreads();
    }

    // epilogue: tanh(acc + ws)*v, reduce over n
#pragma unroll
    for (int ma = 0; ma < 4; ma++) {
        float r0 = 0.f, r1 = 0.f;
#pragma unroll
        for (int na = 0; na < 8; na++) {
            int nl = wn + na * 8 + 2 * t;
            float w0 = sm.ws[nl], w1 = sm.ws[nl + 1];
            float v0 = sm.v[nl],  v1 = sm.v[nl + 1];
            r0 += tanh_fast(acc[ma][na][0] + w0) * v0 + tanh_fast(acc[ma][na][1] + w1) * v1;
            r1 += tanh_fast(acc[ma][na][2] + w0) * v0 + tanh_fast(acc[ma][na][3] + w1) * v1;
        }
        r0 += __shfl_xor_sync(0xffffffffu, r0, 1);
        r0 += __shfl_xor_sync(0xffffffffu, r0, 2);
        r1 += __shfl_xor_sync(0xffffffffu, r1, 1);
        r1 += __shfl_xor_sync(0xffffffffu, r1, 2);
        if (t == 0) {
            atomicAdd(&sm.rowsum[wm + ma * 16 + g], r0);
            atomicAdd(&sm.rowsum[wm + ma * 16 + g + 8], r1);
        }
    }
    __syncthreads();
    if (tid < BM) g_part[blockIdx.x][m_base + tid] = sm.rowsum[tid];
}

// ================= K2: softmax over S per batch =================
__global__ void softmax_kernel(float* __restrict__ wout) {
    __shared__ float sc[Ss];
    __shared__ float red[256];
    int b = blockIdx.x, tid = threadIdx.x;
    float mx = -1e30f;
    for (int i = tid; i < Ss; i += 256) {
        int idx = b * Ss + i;
        float v = g_part[0][idx] + g_part[1][idx] + g_part[2][idx] + g_part[3][idx];
        sc[i] = v;
        mx = fmaxf(mx, v);
    }
    red[tid] = mx; __syncthreads();
    for (int o = 128; o; o >>= 1) { if (tid < o) red[tid] = fmaxf(red[tid], red[tid + o]); __syncthreads(); }
    mx = red[0]; __syncthreads();
    float sum = 0.f;
    for (int i = tid; i < Ss; i += 256) { float e = __expf(sc[i] - mx); sc[i] = e; sum += e; }
    red[tid] = sum; __syncthreads();
    for (int o = 128; o; o >>= 1) { if (tid < o) red[tid] += red[tid + o]; __syncthreads(); }
    float inv = 1.f / red[0];
    for (int i = tid; i < Ss; i += 256) wout[b * Ss + i] = sc[i] * inv;
}

// ================= K3: context[b,h] = sum_s w[b,s] * enc[b,s,h] =================
__global__ void context_kernel(const float* __restrict__ enc, const float* __restrict__ w,
                               float* __restrict__ out) {
    __shared__ float wsh[Ss];
    int b = blockIdx.y;
    int h = blockIdx.x * 256 + threadIdx.x;
    for (int i = threadIdx.x; i < Ss; i += 256) wsh[i] = w[b * Ss + i];
    __syncthreads();
    const float* e = enc + (size_t)b * Ss * Hh + h;
    float a0 = 0.f, a1 = 0.f, a2 = 0.f, a3 = 0.f;
    for (int s = 0; s < Ss; s += 4) {
        a0 += wsh[s + 0] * e[(size_t)(s + 0) * Hh];
        a1 += wsh[s + 1] * e[(size_t)(s + 1) * Hh];
        a2 += wsh[s + 2] * e[(size_t)(s + 2) * Hh];
        a3 += wsh[s + 3] * e[(size_t)(s + 3) * Hh];
    }
    out[b * Hh + h] = (a0 + a1) + (a2 + a3);
}

// ================= launcher =================
extern "C" void kernel_launch(void* const* d_in, const int* in_sizes, int n_in,
                              void* d_out, int out_size) {
    (void)in_sizes; (void)n_in; (void)out_size;
    const float* dec = (const float*)d_in[0];   // [32,1024]
    const float* enc = (const float*)d_in[1];   // [32,2048,1024]
    const float* Wh  = (const float*)d_in[2];   // [1024,1024]
    const float* Wsm = (const float*)d_in[3];   // [1024,1024]
    const float* v   = (const float*)d_in[4];   // [1024]
    float* out  = (float*)d_out;
    float* ctx  = out;                 // [32,1024]
    float* attw = out + Bb * Hh;       // [32,2048]

    cudaFuncSetAttribute(attn_scores_kernel, cudaFuncAttributeMaxDynamicSharedMemorySize,
                         (int)sizeof(SmemK1));

    round_wh_kernel<<<Hh * Hh / 1024, 256>>>(Wh);
    ws_kernel<<<Bb * Hh / 8, 256>>>(dec, Wsm);
    attn_scores_kernel<<<dim3(NT, M_TOTAL / BM), 256, sizeof(SmemK1)>>>(enc, v);
    softmax_kernel<<<Bb, 256>>>(attw);
    context_kernel<<<dim3(Hh / 256, Bb), 256>>>(enc, attw, ctx);
}

// round 3
// speedup vs baseline: 1.0547x; 1.0547x over previous
#include <cuda_runtime.h>
#include <cuda_fp16.h>
#include <cstdint>

#define DEVINL __device__ __forceinline__

// ---------------- problem sizes ----------------
constexpr int Bb = 32, Ss = 2048, Hh = 1024;
constexpr int M_TOTAL = Bb * Ss;          // 65536
constexpr int BM = 128, BN = 256, BK = 32;   // BK in halves (k elements)
constexpr int NSTEPS = Hh / BK;           // 16... wait Hh/BK = 32? 1024/32 = 32
constexpr int NT = Hh / BN;               // 4 N-tiles
constexpr int LDH = 40;                   // padded smem row stride in halves (80B)

// ---------------- scratch (no allocs allowed) ----------------
__device__ float  g_ws[Bb * Hh];          // W_s @ dec
__device__ __half g_wh_h[Hh * Hh];        // fp16 W_h
__device__ float  g_part[NT][M_TOTAL];    // partial scores per N-tile

struct SmemK1 {
    __half A[2][BM][LDH];     // 2*128*80B = 20,480 B
    __half B[2][BN][LDH];     // 2*256*80B = 40,960 B
    float ws[BN];
    float v[BN];
    float rowsum[BM];
};

// ---------------- helpers ----------------
DEVINL uint32_t smem_u32(const void* p) {
    uint32_t a;
    asm("{ .reg .u64 t; cvta.to.shared.u64 t, %1; cvt.u32.u64 %0, t; }" : "=r"(a) : "l"(p));
    return a;
}
DEVINL float tanh_fast(float x) {
    float r;
    asm("tanh.approx.f32 %0, %1;" : "=f"(r) : "f"(x));
    return r;
}
DEVINL void cp_async16(uint32_t dst, const void* src) {
    asm volatile("cp.async.cg.shared.global [%0], [%1], 16;" :: "r"(dst), "l"(src));
}
DEVINL void cp_commit() { asm volatile("cp.async.commit_group;"); }
DEVINL void cp_wait0()  { asm volatile("cp.async.wait_group 0;"); }

DEVINL void ldmatrix_x4(uint32_t r[4], uint32_t addr) {
    asm volatile("ldmatrix.sync.aligned.m8n8.x4.shared.b16 {%0,%1,%2,%3}, [%4];"
                 : "=r"(r[0]), "=r"(r[1]), "=r"(r[2]), "=r"(r[3]) : "r"(addr));
}
DEVINL void mma_f16(float c[4], const uint32_t a[4], const uint32_t b[2]) {
    asm volatile(
        "mma.sync.aligned.m16n8k16.row.col.f32.f16.f16.f32 "
        "{%0,%1,%2,%3}, {%4,%5,%6,%7}, {%8,%9}, {%0,%1,%2,%3};"
        : "+f"(c[0]), "+f"(c[1]), "+f"(c[2]), "+f"(c[3])
        : "r"(a[0]), "r"(a[1]), "r"(a[2]), "r"(a[3]), "r"(b[0]), "r"(b[1]));
}
DEVINL uint32_t pack_h2(float lo, float hi) {
    __half2 h = __floats2half2_rn(lo, hi);
    return *reinterpret_cast<uint32_t*>(&h);
}

// ================= K0a: W_h -> fp16 =================
__global__ void wh_to_half_kernel(const float* __restrict__ Wh) {
    int i = (blockIdx.x * 256 + threadIdx.x) * 4;
    float4 v = *reinterpret_cast<const float4*>(Wh + i);
    uint2 u;
    u.x = pack_h2(v.x, v.y);
    u.y = pack_h2(v.z, v.w);
    *reinterpret_cast<uint2*>(g_wh_h + i) = u;
}

// ================= K0b: ws[b,o] = dec[b,:] . W_s[o,:] (fp32 exact) =================
__global__ void ws_kernel(const float* __restrict__ dec, const float* __restrict__ Wsm) {
    int idx = blockIdx.x * 8 + (threadIdx.x >> 5);
    int lid = threadIdx.x & 31;
    int b = idx >> 10, o = idx & 1023;
    const float* dr = dec + (size_t)b * Hh;
    const float* wr = Wsm + (size_t)o * Hh;
    float acc = 0.f;
#pragma unroll
    for (int i = 0; i < 8; i++) {
        int k = (i * 32 + lid) * 4;
        float4 d4 = *reinterpret_cast<const float4*>(dr + k);
        float4 w4 = *reinterpret_cast<const float4*>(wr + k);
        acc += d4.x * w4.x + d4.y * w4.y + d4.z * w4.z + d4.w * w4.w;
    }
#pragma unroll
    for (int off = 16; off; off >>= 1) acc += __shfl_xor_sync(0xffffffffu, acc, off);
    if (lid == 0) g_ws[idx] = acc;
}

// ================= K1: fused fp16 GEMM + tanh + v-dot -> partial scores =================
__global__ __launch_bounds__(256, 1) void attn_scores_kernel(
    const float* __restrict__ enc, const float* __restrict__ vvec) {
    extern __shared__ char smraw[];
    SmemK1& sm = *reinterpret_cast<SmemK1*>(smraw);

    const int tid = threadIdx.x, wid = tid >> 5, lane = tid & 31;
    const int g = lane >> 2, t = lane & 3;
    const int wm = (wid >> 2) * 64, wn = (wid & 3) * 64;
    const int m_base = blockIdx.y * BM;
    const int n_base = blockIdx.x * BN;
    const int b = m_base >> 11;

    for (int i = tid; i < BN; i += 256) {
        sm.ws[i] = g_ws[b * Hh + n_base + i];
        sm.v[i]  = vvec[n_base + i];
    }
    if (tid < BM) sm.rowsum[tid] = 0.f;

    const float* encp = enc + (size_t)m_base * Hh;

    // A staging: thread -> (row r = tid&127, col-half c = tid>>7), 16 f32 each
    const int ar = tid & 127, ac = tid >> 7;   // ac in 0..1, 16 floats
    float4 areg[4];
    auto ldgA = [&](int k0) {
        const float* src = encp + (size_t)ar * Hh + k0 + ac * 16;
#pragma unroll
        for (int i = 0; i < 4; i++) areg[i] = *reinterpret_cast<const float4*>(src + i * 4);
    };
    auto stsA = [&](int p) {
        uint4 u0, u1;
        u0.x = pack_h2(areg[0].x, areg[0].y); u0.y = pack_h2(areg[0].z, areg[0].w);
        u0.z = pack_h2(areg[1].x, areg[1].y); u0.w = pack_h2(areg[1].z, areg[1].w);
        u1.x = pack_h2(areg[2].x, areg[2].y); u1.y = pack_h2(areg[2].z, areg[2].w);
        u1.z = pack_h2(areg[3].x, areg[3].y); u1.w = pack_h2(areg[3].z, areg[3].w);
        char* dst = reinterpret_cast<char*>(&sm.A[p][ar][0]) + ac * 32;
        *reinterpret_cast<uint4*>(dst)      = u0;
        *reinterpret_cast<uint4*>(dst + 16) = u1;
    };
    // B staging via cp.async: 256 rows * 4 chunks of 16B
    auto cpB = [&](int p, int k0) {
#pragma unroll
        for (int i = 0; i < 4; i++) {
            int chunk = tid + i * 256;
            int r = chunk & 255, c = chunk >> 8;
            cp_async16(smem_u32(reinterpret_cast<char*>(&sm.B[p][r][0]) + c * 16),
                       g_wh_h + (size_t)(n_base + r) * Hh + k0 + c * 8);
        }
        cp_commit();
    };

    float acc[4][8][4];
#pragma unroll
    for (int ma = 0; ma < 4; ma++)
#pragma unroll
        for (int na = 0; na < 8; na++)
#pragma unroll
            for (int r = 0; r < 4; r++) acc[ma][na][r] = 0.f;

    // lane offsets for ldmatrix (bytes): sel = lane>>3
    const int lr  = lane & 7, sel = lane >> 3;
    const uint32_t lane_off = (uint32_t)((lr + (sel & 1) * 8) * (LDH * 2) + (sel >> 1) * 16);
    const uint32_t baseA[2] = { smem_u32(&sm.A[0][0][0]), smem_u32(&sm.A[1][0][0]) };
    const uint32_t baseB[2] = { smem_u32(&sm.B[0][0][0]), smem_u32(&sm.B[1][0][0]) };

    // prologue
    ldgA(0); cpB(0, 0);
    stsA(0);
    cp_wait0();
    __syncthreads();

    constexpr int STAGES = Hh / BK;   // 32
#pragma unroll 1
    for (int s = 0; s < STAGES; s++) {
        int p = s & 1;
        if (s + 1 < STAGES) { ldgA((s + 1) * BK); cpB(1 - p, (s + 1) * BK); }

        uint32_t aw = baseA[p] + (uint32_t)(wm * (LDH * 2)) + lane_off;
        uint32_t bw = baseB[p] + (uint32_t)(wn * (LDH * 2)) + lane_off;
#pragma unroll
        for (int ka = 0; ka < 2; ka++) {
            uint32_t af[4][4];
#pragma unroll
            for (int ma = 0; ma < 4; ma++)
                ldmatrix_x4(af[ma], aw + (uint32_t)(ma * 16 * (LDH * 2)) + ka * 32);
            uint32_t bf[8][2];
#pragma unroll
            for (int nb = 0; nb < 4; nb++) {
                uint32_t r[4];
                ldmatrix_x4(r, bw + (uint32_t)(nb * 16 * (LDH * 2)) + ka * 32);
                bf[2 * nb][0] = r[0]; bf[2 * nb + 1][0] = r[1];
                bf[2 * nb][1] = r[2]; bf[2 * nb + 1][1] = r[3];
            }
#pragma unroll
            for (int ma = 0; ma < 4; ma++)
#pragma unroll
                for (int na = 0; na < 8; na++)
                    mma_f16(acc[ma][na], af[ma], bf[na]);
        }

        if (s + 1 < STAGES) { stsA(1 - p); cp_wait0(); }
        __syncthreads();
    }

    // epilogue: tanh(acc + ws)*v, reduce over n
#pragma unroll
    for (int ma = 0; ma < 4; ma++) {
        float r0 = 0.f, r1 = 0.f;
#pragma unroll
        for (int na = 0; na < 8; na++) {
            int nl = wn + na * 8 + 2 * t;
            float w0 = sm.ws[nl], w1 = sm.ws[nl + 1];
            float v0 = sm.v[nl],  v1 = sm.v[nl + 1];
            r0 += tanh_fast(acc[ma][na][0] + w0) * v0 + tanh_fast(acc[ma][na][1] + w1) * v1;
            r1 += tanh_fast(acc[ma][na][2] + w0) * v0 + tanh_fast(acc[ma][na][3] + w1) * v1;
        }
        r0 += __shfl_xor_sync(0xffffffffu, r0, 1);
        r0 += __shfl_xor_sync(0xffffffffu, r0, 2);
        r1 += __shfl_xor_sync(0xffffffffu, r1, 1);
        r1 += __shfl_xor_sync(0xffffffffu, r1, 2);
        if (t == 0) {
            atomicAdd(&sm.rowsum[wm + ma * 16 + g], r0);
            atomicAdd(&sm.rowsum[wm + ma * 16 + g + 8], r1);
        }
    }
    __syncthreads();
    if (tid < BM) g_part[blockIdx.x][m_base + tid] = sm.rowsum[tid];
}

// ================= K2: softmax over S per batch =================
__global__ void softmax_kernel(float* __restrict__ wout) {
    __shared__ float sc[Ss];
    __shared__ float red[256];
    int b = blockIdx.x, tid = threadIdx.x;
    float mx = -1e30f;
    for (int i = tid; i < Ss; i += 256) {
        int idx = b * Ss + i;
        float v = g_part[0][idx] + g_part[1][idx] + g_part[2][idx] + g_part[3][idx];
        sc[i] = v;
        mx = fmaxf(mx, v);
    }
    red[tid] = mx; __syncthreads();
    for (int o = 128; o; o >>= 1) { if (tid < o) red[tid] = fmaxf(red[tid], red[tid + o]); __syncthreads(); }
    mx = red[0]; __syncthreads();
    float sum = 0.f;
    for (int i = tid; i < Ss; i += 256) { float e = __expf(sc[i] - mx); sc[i] = e; sum += e; }
    red[tid] = sum; __syncthreads();
    for (int o = 128; o; o >>= 1) { if (tid < o) red[tid] += red[tid + o]; __syncthreads(); }
    float inv = 1.f / red[0];
    for (int i = tid; i < Ss; i += 256) wout[b * Ss + i] = sc[i] * inv;
}

// ================= K3: context[b,h] = sum_s w[b,s] * enc[b,s,h] =================
__global__ void context_kernel(const float* __restrict__ enc, const float* __restrict__ w,
                               float* __restrict__ out) {
    __shared__ float wsh[Ss];
    int b = blockIdx.y;
    int h = blockIdx.x * 256 + threadIdx.x;
    for (int i = threadIdx.x; i < Ss; i += 256) wsh[i] = w[b * Ss + i];
    __syncthreads();
    const float* e = enc + (size_t)b * Ss * Hh + h;
    float a0 = 0.f, a1 = 0.f, a2 = 0.f, a3 = 0.f;
    for (int s = 0; s < Ss; s += 4) {
        a0 += wsh[s + 0] * e[(size_t)(s + 0) * Hh];
        a1 += wsh[s + 1] * e[(size_t)(s + 1) * Hh];
        a2 += wsh[s + 2] * e[(size_t)(s + 2) * Hh];
        a3 += wsh[s + 3] * e[(size_t)(s + 3) * Hh];
    }
    out[b * Hh + h] = (a0 + a1) + (a2 + a3);
}

// ================= launcher =================
extern "C" void kernel_launch(void* const* d_in, const int* in_sizes, int n_in,
                              void* d_out, int out_size) {
    (void)in_sizes; (void)n_in; (void)out_size;
    const float* dec = (const float*)d_in[0];   // [32,1024]
    const float* enc = (const float*)d_in[1];   // [32,2048,1024]
    const float* Wh  = (const float*)d_in[2];   // [1024,1024]
    const float* Wsm = (const float*)d_in[3];   // [1024,1024]
    const float* v   = (const float*)d_in[4];   // [1024]
    float* out  = (float*)d_out;
    float* ctx  = out;                 // [32,1024]
    float* attw = out + Bb * Hh;       // [32,2048]

    cudaFuncSetAttribute(attn_scores_kernel, cudaFuncAttributeMaxDynamicSharedMemorySize,
                         (int)sizeof(SmemK1));

    wh_to_half_kernel<<<Hh * Hh / 1024, 256>>>(Wh);
    ws_kernel<<<Bb * Hh / 8, 256>>>(dec, Wsm);
    attn_scores_kernel<<<dim3(NT, M_TOTAL / BM), 256, sizeof(SmemK1)>>>(enc, v);
    softmax_kernel<<<Bb, 256>>>(attw);
    context_kernel<<<dim3(Hh / 256, Bb), 256>>>(enc, attw, ctx);
}

// round 4
// speedup vs baseline: 1.4082x; 1.3351x over previous
#include <cuda_runtime.h>
#include <cuda_fp16.h>
#include <cstdint>

#define DEVINL __device__ __forceinline__

// ---------------- problem sizes ----------------
constexpr int Bb = 32, Ss = 2048, Hh = 1024;
constexpr int M_TOTAL = Bb * Ss;          // 65536
constexpr int BM = 128, BN = 256, BK = 32;   // K-step = 32 elements
constexpr int NSTEPS = Hh / BK;           // 32
constexpr int NT = Hh / BN;               // 4 N-tiles
constexpr int LDH = 40;                   // padded smem row stride in halves (80B)
constexpr int PIPE = 4;                   // cp.async stages

// ---------------- scratch (no allocs allowed) ----------------
__device__ float  g_ws[Bb * Hh];          // W_s @ dec
__device__ __half g_wh_h[Hh * Hh];        // fp16 W_h
__device__ __half g_enc_h[(size_t)M_TOTAL * Hh];  // fp16 encoder (128 MB)
__device__ float  g_part[NT][M_TOTAL];    // partial scores per N-tile

struct SmemK1 {
    __half A[PIPE][BM][LDH];   // 4*128*80B = 40,960 B
    __half B[PIPE][BN][LDH];   // 4*256*80B = 81,920 B
    float ws[BN];
    float v[BN];
    float rowsum[BM];
};

// ---------------- helpers ----------------
DEVINL uint32_t smem_u32(const void* p) {
    uint32_t a;
    asm("{ .reg .u64 t; cvta.to.shared.u64 t, %1; cvt.u32.u64 %0, t; }" : "=r"(a) : "l"(p));
    return a;
}
DEVINL float tanh_fast(float x) {
    float r;
    asm("tanh.approx.f32 %0, %1;" : "=f"(r) : "f"(x));
    return r;
}
DEVINL void cp_async16(uint32_t dst, const void* src) {
    asm volatile("cp.async.cg.shared.global [%0], [%1], 16;" :: "r"(dst), "l"(src));
}
DEVINL void cp_commit() { asm volatile("cp.async.commit_group;"); }
DEVINL void cp_wait3()  { asm volatile("cp.async.wait_group 3;"); }
DEVINL void cp_wait2()  { asm volatile("cp.async.wait_group 2;"); }

DEVINL void ldmatrix_x4(uint32_t r[4], uint32_t addr) {
    asm volatile("ldmatrix.sync.aligned.m8n8.x4.shared.b16 {%0,%1,%2,%3}, [%4];"
                 : "=r"(r[0]), "=r"(r[1]), "=r"(r[2]), "=r"(r[3]) : "r"(addr));
}
DEVINL void mma_f16(float c[4], const uint32_t a[4], const uint32_t b[2]) {
    asm volatile(
        "mma.sync.aligned.m16n8k16.row.col.f32.f16.f16.f32 "
        "{%0,%1,%2,%3}, {%4,%5,%6,%7}, {%8,%9}, {%0,%1,%2,%3};"
        : "+f"(c[0]), "+f"(c[1]), "+f"(c[2]), "+f"(c[3])
        : "r"(a[0]), "r"(a[1]), "r"(a[2]), "r"(a[3]), "r"(b[0]), "r"(b[1]));
}
DEVINL uint32_t pack_h2(float lo, float hi) {
    __half2 h = __floats2half2_rn(lo, hi);
    return *reinterpret_cast<uint32_t*>(&h);
}

// ================= K0a: W_h -> fp16 =================
__global__ void wh_to_half_kernel(const float* __restrict__ Wh) {
    int i = (blockIdx.x * 256 + threadIdx.x) * 4;
    float4 v = *reinterpret_cast<const float4*>(Wh + i);
    uint2 u;
    u.x = pack_h2(v.x, v.y);
    u.y = pack_h2(v.z, v.w);
    *reinterpret_cast<uint2*>(g_wh_h + i) = u;
}

// ================= K0c: enc -> fp16 (8 elements/thread) =================
__global__ void enc_to_half_kernel(const float* __restrict__ enc) {
    size_t i = ((size_t)blockIdx.x * 256 + threadIdx.x) * 8;
    float4 v0 = *reinterpret_cast<const float4*>(enc + i);
    float4 v1 = *reinterpret_cast<const float4*>(enc + i + 4);
    uint4 u;
    u.x = pack_h2(v0.x, v0.y); u.y = pack_h2(v0.z, v0.w);
    u.z = pack_h2(v1.x, v1.y); u.w = pack_h2(v1.z, v1.w);
    *reinterpret_cast<uint4*>(g_enc_h + i) = u;
}

// ================= K0b: ws[b,o] = dec[b,:] . W_s[o,:] (fp32 exact) =================
__global__ void ws_kernel(const float* __restrict__ dec, const float* __restrict__ Wsm) {
    int idx = blockIdx.x * 8 + (threadIdx.x >> 5);
    int lid = threadIdx.x & 31;
    int b = idx >> 10, o = idx & 1023;
    const float* dr = dec + (size_t)b * Hh;
    const float* wr = Wsm + (size_t)o * Hh;
    float acc = 0.f;
#pragma unroll
    for (int i = 0; i < 8; i++) {
        int k = (i * 32 + lid) * 4;
        float4 d4 = *reinterpret_cast<const float4*>(dr + k);
        float4 w4 = *reinterpret_cast<const float4*>(wr + k);
        acc += d4.x * w4.x + d4.y * w4.y + d4.z * w4.z + d4.w * w4.w;
    }
#pragma unroll
    for (int off = 16; off; off >>= 1) acc += __shfl_xor_sync(0xffffffffu, acc, off);
    if (lid == 0) g_ws[idx] = acc;
}

// ================= K1: fused fp16 GEMM + tanh + v-dot -> partial scores =================
__global__ __launch_bounds__(256, 1) void attn_scores_kernel(const float* __restrict__ vvec) {
    extern __shared__ char smraw[];
    SmemK1& sm = *reinterpret_cast<SmemK1*>(smraw);

    const int tid = threadIdx.x, wid = tid >> 5, lane = tid & 31;
    const int g = lane >> 2, t = lane & 3;
    const int wm = (wid >> 2) * 64, wn = (wid & 3) * 64;
    const int m_base = blockIdx.y * BM;
    const int n_base = blockIdx.x * BN;
    const int b = m_base >> 11;

    for (int i = tid; i < BN; i += 256) {
        sm.ws[i] = g_ws[b * Hh + n_base + i];
        sm.v[i]  = vvec[n_base + i];
    }
    if (tid < BM) sm.rowsum[tid] = 0.f;

    // per-thread cp.async chunk coordinates (16B chunks, 4 per 64B row)
    const int rA = tid >> 2, cA = tid & 3;            // + i*64 rows, i<2
    const int rB = tid >> 2, cB = tid & 3;            // + i*64 rows, i<4
    const __half* srcA = g_enc_h + (size_t)(m_base + rA) * Hh + cA * 8;
    const __half* srcB = g_wh_h  + (size_t)(n_base + rB) * Hh + cB * 8;

    auto issue_stage = [&](int stage, int k0) {
#pragma unroll
        for (int i = 0; i < 2; i++)
            cp_async16(smem_u32(reinterpret_cast<char*>(&sm.A[stage][rA + i * 64][0]) + cA * 16),
                       srcA + (size_t)(i * 64) * Hh + k0);
#pragma unroll
        for (int i = 0; i < 4; i++)
            cp_async16(smem_u32(reinterpret_cast<char*>(&sm.B[stage][rB + i * 64][0]) + cB * 16),
                       srcB + (size_t)(i * 64) * Hh + k0);
        cp_commit();
    };

    float acc[4][8][4];
#pragma unroll
    for (int ma = 0; ma < 4; ma++)
#pragma unroll
        for (int na = 0; na < 8; na++)
#pragma unroll
            for (int r = 0; r < 4; r++) acc[ma][na][r] = 0.f;

    // ldmatrix lane offset
    const int lr = lane & 7, sel = lane >> 3;
    const uint32_t lane_off = (uint32_t)((lr + (sel & 1) * 8) * (LDH * 2) + (sel >> 1) * 16);
    const uint32_t baseA = smem_u32(&sm.A[0][0][0]);
    const uint32_t baseB = smem_u32(&sm.B[0][0][0]);
    constexpr uint32_t A_STRIDE = BM * LDH * 2;   // 10240 B per stage
    constexpr uint32_t B_STRIDE = BN * LDH * 2;   // 20480 B per stage

    // prologue: fill stages 0..2
    issue_stage(0, 0);
    issue_stage(1, BK);
    issue_stage(2, 2 * BK);

#pragma unroll 1
    for (int s = 0; s < NSTEPS; s++) {
        int p = s & (PIPE - 1);
        if (s + 3 < NSTEPS) issue_stage((s + 3) & (PIPE - 1), (s + 3) * BK);
        else                cp_commit();             // empty group keeps count uniform
        cp_wait3();                                  // stage s complete
        __syncthreads();                             // ... and visible to all warps

        uint32_t aw = baseA + p * A_STRIDE + (uint32_t)(wm * (LDH * 2)) + lane_off;
        uint32_t bw = baseB + p * B_STRIDE + (uint32_t)(wn * (LDH * 2)) + lane_off;
#pragma unroll
        for (int ka = 0; ka < 2; ka++) {
            uint32_t af[4][4];
#pragma unroll
            for (int ma = 0; ma < 4; ma++)
                ldmatrix_x4(af[ma], aw + (uint32_t)(ma * 16 * (LDH * 2)) + ka * 32);
            uint32_t bf[8][2];
#pragma unroll
            for (int nb = 0; nb < 4; nb++) {
                uint32_t r[4];
                ldmatrix_x4(r, bw + (uint32_t)(nb * 16 * (LDH * 2)) + ka * 32);
                bf[2 * nb][0] = r[0]; bf[2 * nb + 1][0] = r[1];
                bf[2 * nb][1] = r[2]; bf[2 * nb + 1][1] = r[3];
            }
#pragma unroll
            for (int ma = 0; ma < 4; ma++)
#pragma unroll
                for (int na = 0; na < 8; na++)
                    mma_f16(acc[ma][na], af[ma], bf[na]);
        }
        __syncthreads();   // all reads of stage s done before it is refilled (stage s+4)
    }

    // epilogue: tanh(acc + ws)*v, reduce over n
#pragma unroll
    for (int ma = 0; ma < 4; ma++) {
        float r0 = 0.f, r1 = 0.f;
#pragma unroll
        for (int na = 0; na < 8; na++) {
            int nl = wn + na * 8 + 2 * t;
            float w0 = sm.ws[nl], w1 = sm.ws[nl + 1];
            float v0 = sm.v[nl],  v1 = sm.v[nl + 1];
            r0 += tanh_fast(acc[ma][na][0] + w0) * v0 + tanh_fast(acc[ma][na][1] + w1) * v1;
            r1 += tanh_fast(acc[ma][na][2] + w0) * v0 + tanh_fast(acc[ma][na][3] + w1) * v1;
        }
        r0 += __shfl_xor_sync(0xffffffffu, r0, 1);
        r0 += __shfl_xor_sync(0xffffffffu, r0, 2);
        r1 += __shfl_xor_sync(0xffffffffu, r1, 1);
        r1 += __shfl_xor_sync(0xffffffffu, r1, 2);
        if (t == 0) {
            atomicAdd(&sm.rowsum[wm + ma * 16 + g], r0);
            atomicAdd(&sm.rowsum[wm + ma * 16 + g + 8], r1);
        }
    }
    __syncthreads();
    if (tid < BM) g_part[blockIdx.x][m_base + tid] = sm.rowsum[tid];
}

// ================= K2: softmax over S per batch =================
__global__ void softmax_kernel(float* __restrict__ wout) {
    __shared__ float sc[Ss];
    __shared__ float red[256];
    int b = blockIdx.x, tid = threadIdx.x;
    float mx = -1e30f;
    for (int i = tid; i < Ss; i += 256) {
        int idx = b * Ss + i;
        float v = g_part[0][idx] + g_part[1][idx] + g_part[2][idx] + g_part[3][idx];
        sc[i] = v;
        mx = fmaxf(mx, v);
    }
    red[tid] = mx; __syncthreads();
    for (int o = 128; o; o >>= 1) { if (tid < o) red[tid] = fmaxf(red[tid], red[tid + o]); __syncthreads(); }
    mx = red[0]; __syncthreads();
    float sum = 0.f;
    for (int i = tid; i < Ss; i += 256) { float e = __expf(sc[i] - mx); sc[i] = e; sum += e; }
    red[tid] = sum; __syncthreads();
    for (int o = 128; o; o >>= 1) { if (tid < o) red[tid] += red[tid + o]; __syncthreads(); }
    float inv = 1.f / red[0];
    for (int i = tid; i < Ss; i += 256) wout[b * Ss + i] = sc[i] * inv;
}

// ================= K3: context[b,h] = sum_s w[b,s] * enc[b,s,h] =================
__global__ void context_kernel(const float* __restrict__ enc, const float* __restrict__ w,
                               float* __restrict__ out) {
    __shared__ float wsh[Ss];
    int b = blockIdx.y;
    int h = blockIdx.x * 256 + threadIdx.x;
    for (int i = threadIdx.x; i < Ss; i += 256) wsh[i] = w[b * Ss + i];
    __syncthreads();
    const float* e = enc + (size_t)b * Ss * Hh + h;
    float a0 = 0.f, a1 = 0.f, a2 = 0.f, a3 = 0.f;
    for (int s = 0; s < Ss; s += 4) {
        a0 += wsh[s + 0] * e[(size_t)(s + 0) * Hh];
        a1 += wsh[s + 1] * e[(size_t)(s + 1) * Hh];
        a2 += wsh[s + 2] * e[(size_t)(s + 2) * Hh];
        a3 += wsh[s + 3] * e[(size_t)(s + 3) * Hh];
    }
    out[b * Hh + h] = (a0 + a1) + (a2 + a3);
}

// ================= launcher =================
extern "C" void kernel_launch(void* const* d_in, const int* in_sizes, int n_in,
                              void* d_out, int out_size) {
    (void)in_sizes; (void)n_in; (void)out_size;
    const float* dec = (const float*)d_in[0];   // [32,1024]
    const float* enc = (const float*)d_in[1];   // [32,2048,1024]
    const float* Wh  = (const float*)d_in[2];   // [1024,1024]
    const float* Wsm = (const float*)d_in[3];   // [1024,1024]
    const float* v   = (const float*)d_in[4];   // [1024]
    float* out  = (float*)d_out;
    float* ctx  = out;                 // [32,1024]
    float* attw = out + Bb * Hh;       // [32,2048]

    cudaFuncSetAttribute(attn_scores_kernel, cudaFuncAttributeMaxDynamicSharedMemorySize,
                         (int)sizeof(SmemK1));

    wh_to_half_kernel<<<Hh * Hh / 1024, 256>>>(Wh);
    enc_to_half_kernel<<<(int)((size_t)M_TOTAL * Hh / 2048), 256>>>(enc);
    ws_kernel<<<Bb * Hh / 8, 256>>>(dec, Wsm);
    attn_scores_kernel<<<dim3(NT, M_TOTAL / BM), 256, sizeof(SmemK1)>>>(v);
    softmax_kernel<<<Bb, 256>>>(attw);
    context_kernel<<<dim3(Hh / 256, Bb), 256>>>(enc, attw, ctx);
}